// round 8
// baseline (speedup 1.0000x reference)
#include <cuda_runtime.h>
#include <cuda_bf16.h>

// Cumulative mean over axis 0 of x[8192, 4096] fp32:
//   out[r, c] = (sum_{i<=r} x[i, c]) / (r + 1)
//
// Chunked 3-pass scan: rows split into 4 chunks of 2048. Per chunk:
//   k_partial : per-16-row-tile column sums -> g_part   (DRAM read of chunk)
//   k_scan    : inclusive scan of chunk's 128 tiles, carry from prev chunk
//   k_final   : re-read chunk (L2-resident), scan+scale+store (__stcs)
// The chunk (32 MB) + its output (32 MB) fit in L2, so k_final's x reads hit.

#define ROWS    8192
#define COLS    4096
#define TPB     256
#define C4      (COLS / 4)             // 1024 float4 per row
#define NCB     (COLS / (TPB * 4))     // 4 column blocks (1024 cols each)

#define T1      16                     // tile rows (both passes)
#define NT1     (ROWS / T1)            // 512 tiles total
#define CHROWS  2048                   // rows per chunk
#define NCHUNK  (ROWS / CHROWS)        // 4
#define TPC     (CHROWS / T1)          // 128 tiles per chunk

// Static device scratch (no allocation allowed anywhere).
__device__ float4 g_part[NT1 * C4];    // [tile][col4], 8 MB (scanned in place)
__device__ float  g_inv[ROWS];         // 1/(r+1), 32 KB

__device__ __forceinline__ float4 f4_add(float4 a, float4 b) {
    a.x += b.x; a.y += b.y; a.z += b.z; a.w += b.w;
    return a;
}

// ---------------- Pass 1 (per chunk): per-tile partial sums ------------------
__global__ void __launch_bounds__(TPB)
k_partial(const float* __restrict__ x, int tile0) {
    const int bx  = blockIdx.x;
    const int rt  = tile0 + bx / NCB;        // global tile id
    const int cb  = bx % NCB;
    const int tid = threadIdx.x;

    // Fill the reciprocal table once (first chunk only).
    if (tile0 == 0) {
        const int gt = bx * TPB + tid;
        if (gt < ROWS) g_inv[gt] = 1.0f / (float)(gt + 1);
    }

    const float4* __restrict__ x4 = reinterpret_cast<const float4*>(x);
    const int col4 = cb * TPB + tid;
    const int base = rt * T1 * C4 + col4;

    float4 a0 = make_float4(0.f, 0.f, 0.f, 0.f);
    float4 a1 = a0, a2 = a0, a3 = a0;
#pragma unroll
    for (int r = 0; r < T1; r += 4) {
        float4 v0 = __ldg(&x4[base + (r + 0) * C4]);
        float4 v1 = __ldg(&x4[base + (r + 1) * C4]);
        float4 v2 = __ldg(&x4[base + (r + 2) * C4]);
        float4 v3 = __ldg(&x4[base + (r + 3) * C4]);
        a0 = f4_add(a0, v0);
        a1 = f4_add(a1, v1);
        a2 = f4_add(a2, v2);
        a3 = f4_add(a3, v3);
    }
    g_part[rt * C4 + col4] = f4_add(f4_add(a0, a1), f4_add(a2, a3));
}

// ------ Pass 2 (per chunk): scan chunk tiles, carry from previous chunk ------
__global__ void __launch_bounds__(TPB)
k_scan(int tile0) {
    const int t = blockIdx.x * TPB + threadIdx.x;   // 0..1023, one col4 each

    // Carry = inclusive prefix of previous chunk's last tile (already scanned).
    float4 run = (tile0 == 0) ? make_float4(0.f, 0.f, 0.f, 0.f)
                              : g_part[(tile0 - 1) * C4 + t];

    // Batch-8 register staging: 8 independent loads, then 8 add+stores.
    // Breaks the load->store alias chain so latency is exposed once per batch.
    for (int b = 0; b < TPC; b += 8) {
        float4 v[8];
#pragma unroll
        for (int j = 0; j < 8; j++)
            v[j] = g_part[(tile0 + b + j) * C4 + t];
#pragma unroll
        for (int j = 0; j < 8; j++) {
            run = f4_add(run, v[j]);
            g_part[(tile0 + b + j) * C4 + t] = run;   // inclusive prefix
        }
    }
}

// ------ Pass 3 (per chunk): streaming final scan + scale + store -------------
__global__ void __launch_bounds__(TPB)
k_final(const float* __restrict__ x, float* __restrict__ out, int tile0) {
    const int bx  = blockIdx.x;
    const int rt  = tile0 + bx / NCB;        // global tile id
    const int cb  = bx % NCB;
    const int tid = threadIdx.x;

    const float4* __restrict__ x4 = reinterpret_cast<const float4*>(x);
    float4*       __restrict__ o4 = reinterpret_cast<float4*>(out);
    const int col4 = cb * TPB + tid;
    const int base = rt * T1 * C4 + col4;
    const int row0 = rt * T1;

    // Exclusive prefix = scanned inclusive prefix of the previous tile.
    float4 run = (rt == 0) ? make_float4(0.f, 0.f, 0.f, 0.f)
                           : __ldg(&g_part[(rt - 1) * C4 + col4]);

#pragma unroll
    for (int r = 0; r < T1; r += 4) {
        float4 v0 = __ldg(&x4[base + (r + 0) * C4]);
        float4 v1 = __ldg(&x4[base + (r + 1) * C4]);
        float4 v2 = __ldg(&x4[base + (r + 2) * C4]);
        float4 v3 = __ldg(&x4[base + (r + 3) * C4]);

        const float i0 = g_inv[row0 + r + 0];
        const float i1 = g_inv[row0 + r + 1];
        const float i2 = g_inv[row0 + r + 2];
        const float i3 = g_inv[row0 + r + 3];

        float4 o;
        run = f4_add(run, v0);
        o.x = run.x * i0; o.y = run.y * i0; o.z = run.z * i0; o.w = run.w * i0;
        __stcs(&o4[base + (r + 0) * C4], o);

        run = f4_add(run, v1);
        o.x = run.x * i1; o.y = run.y * i1; o.z = run.z * i1; o.w = run.w * i1;
        __stcs(&o4[base + (r + 1) * C4], o);

        run = f4_add(run, v2);
        o.x = run.x * i2; o.y = run.y * i2; o.z = run.z * i2; o.w = run.w * i2;
        __stcs(&o4[base + (r + 2) * C4], o);

        run = f4_add(run, v3);
        o.x = run.x * i3; o.y = run.y * i3; o.z = run.z * i3; o.w = run.w * i3;
        __stcs(&o4[base + (r + 3) * C4], o);
    }
}

extern "C" void kernel_launch(void* const* d_in, const int* in_sizes, int n_in,
                              void* d_out, int out_size) {
    const float* x   = (const float*)d_in[0];
    float*       out = (float*)d_out;

    for (int c = 0; c < NCHUNK; c++) {
        const int tile0 = c * TPC;
        k_partial<<<TPC * NCB, TPB>>>(x, tile0);
        k_scan<<<C4 / TPB, TPB>>>(tile0);
        k_final<<<TPC * NCB, TPB>>>(x, out, tile0);
    }
}

// round 10
// speedup vs baseline: 1.5234x; 1.5234x over previous
#include <cuda_runtime.h>
#include <cuda_bf16.h>

// Cumulative mean over axis 0 of x[8192, 4096] fp32:
//   out[r, c] = (sum_{i<=r} x[i, c]) / (r + 1)
//
// 3-pass reduce-then-scan (serial chain minimized):
//   k_partial : 16-row tile column sums -> g_part[512]     (reads x, 5.9 TB/s)
//   k_scan    : fold 4 partials -> 64-row sums in registers, inclusive scan
//               over 128 entries per scalar column, write g_s64 prefixes
//   k_final   : 64-row tiles, run = g_s64[rt-1] + streaming scan of x,
//               out = run * inv, __stcs stores

#define ROWS   8192
#define COLS   4096
#define C4     (COLS / 4)             // 1024 float4 per row

// ---- pass 1 geometry (proven 5.9 TB/s) ----
#define TPB1   256
#define T1     16
#define NT1    (ROWS / T1)            // 512
#define NCB1   (COLS / (TPB1 * 4))    // 4

// ---- 64-row scan geometry ----
#define T3     64
#define NT3    (ROWS / T3)            // 128

// ---- pass 3 geometry (R3-proven shape) ----
#define TPB3   128
#define NCB3   (COLS / (TPB3 * 4))    // 8

// Static device scratch (no allocation allowed anywhere).
__device__ float4 g_part[NT1 * C4];   // raw 16-row sums, 8 MB
__device__ float4 g_s64[NT3 * C4];    // inclusive 64-row prefixes, 2 MB
__device__ float  g_inv[ROWS];        // 1/(r+1)

__device__ __forceinline__ float4 f4_add(float4 a, float4 b) {
    a.x += b.x; a.y += b.y; a.z += b.z; a.w += b.w;
    return a;
}

// ---------------- Pass 1: 16-row tile partial sums (+ inv table) -------------
__global__ void __launch_bounds__(TPB1)
k_partial(const float* __restrict__ x) {
    const int bx  = blockIdx.x;
    const int rt  = bx / NCB1;
    const int cb  = bx % NCB1;
    const int tid = threadIdx.x;

    const int gt = bx * TPB1 + tid;
    if (gt < ROWS) g_inv[gt] = 1.0f / (float)(gt + 1);

    const float4* __restrict__ x4 = reinterpret_cast<const float4*>(x);
    const int col4 = cb * TPB1 + tid;
    const int base = rt * T1 * C4 + col4;

    float4 a0 = make_float4(0.f, 0.f, 0.f, 0.f);
    float4 a1 = a0, a2 = a0, a3 = a0;
#pragma unroll
    for (int r = 0; r < T1; r += 4) {
        float4 v0 = __ldg(&x4[base + (r + 0) * C4]);
        float4 v1 = __ldg(&x4[base + (r + 1) * C4]);
        float4 v2 = __ldg(&x4[base + (r + 2) * C4]);
        float4 v3 = __ldg(&x4[base + (r + 3) * C4]);
        a0 = f4_add(a0, v0);
        a1 = f4_add(a1, v1);
        a2 = f4_add(a2, v2);
        a3 = f4_add(a3, v3);
    }
    g_part[rt * C4 + col4] = f4_add(f4_add(a0, a1), f4_add(a2, a3));
}

// ------- Pass 2: fold 4x16-row partials + scan 128 entries per column --------
__global__ void __launch_bounds__(256)
k_scan() {
    // 4096 threads, one scalar float column each.
    // g_part viewed as float[NT1][COLS]; g_s64 as float[NT3][COLS].
    const float* gp = reinterpret_cast<const float*>(g_part);
    float*       gs = reinterpret_cast<float*>(g_s64);
    const int col = blockIdx.x * 256 + threadIdx.x;

    float run = 0.f;
    // 16 batches of 8 groups; each group = 4 consecutive 16-row partials.
    for (int b = 0; b < NT3; b += 8) {
        float v[32];
#pragma unroll
        for (int j = 0; j < 32; j++)
            v[j] = gp[((b * 4) + j) * COLS + col];    // 32 independent loads
#pragma unroll
        for (int g = 0; g < 8; g++) {
            run += v[g * 4 + 0] + v[g * 4 + 1] + v[g * 4 + 2] + v[g * 4 + 3];
            gs[(b + g) * COLS + col] = run;           // inclusive 64-row prefix
        }
    }
}

// ---------------- Pass 3: streaming final scan + scale + store ---------------
__global__ void __launch_bounds__(TPB3)
k_final(const float* __restrict__ x, float* __restrict__ out) {
    const int bx  = blockIdx.x;
    const int rt  = bx / NCB3;            // 64-row tile
    const int cb  = bx % NCB3;
    const int tid = threadIdx.x;

    const float4* __restrict__ x4 = reinterpret_cast<const float4*>(x);
    float4*       __restrict__ o4 = reinterpret_cast<float4*>(out);
    const int col4 = cb * TPB3 + tid;
    const int base = rt * T3 * C4 + col4;
    const int row0 = rt * T3;

    // Exclusive prefix for this 64-row tile.
    float4 run = (rt == 0) ? make_float4(0.f, 0.f, 0.f, 0.f)
                           : __ldg(&g_s64[(rt - 1) * C4 + col4]);

#pragma unroll 4
    for (int r = 0; r < T3; r += 4) {
        float4 v0 = __ldg(&x4[base + (r + 0) * C4]);
        float4 v1 = __ldg(&x4[base + (r + 1) * C4]);
        float4 v2 = __ldg(&x4[base + (r + 2) * C4]);
        float4 v3 = __ldg(&x4[base + (r + 3) * C4]);

        const float i0 = g_inv[row0 + r + 0];
        const float i1 = g_inv[row0 + r + 1];
        const float i2 = g_inv[row0 + r + 2];
        const float i3 = g_inv[row0 + r + 3];

        float4 o;
        run = f4_add(run, v0);
        o.x = run.x * i0; o.y = run.y * i0; o.z = run.z * i0; o.w = run.w * i0;
        __stcs(&o4[base + (r + 0) * C4], o);

        run = f4_add(run, v1);
        o.x = run.x * i1; o.y = run.y * i1; o.z = run.z * i1; o.w = run.w * i1;
        __stcs(&o4[base + (r + 1) * C4], o);

        run = f4_add(run, v2);
        o.x = run.x * i2; o.y = run.y * i2; o.z = run.z * i2; o.w = run.w * i2;
        __stcs(&o4[base + (r + 2) * C4], o);

        run = f4_add(run, v3);
        o.x = run.x * i3; o.y = run.y * i3; o.z = run.z * i3; o.w = run.w * i3;
        __stcs(&o4[base + (r + 3) * C4], o);
    }
}

extern "C" void kernel_launch(void* const* d_in, const int* in_sizes, int n_in,
                              void* d_out, int out_size) {
    const float* x   = (const float*)d_in[0];
    float*       out = (float*)d_out;

    k_partial<<<NT1 * NCB1, TPB1>>>(x);
    k_scan<<<COLS / 256, 256>>>();
    k_final<<<NT3 * NCB3, TPB3>>>(x, out);
}

// round 13
// speedup vs baseline: 1.6459x; 1.0804x over previous
#include <cuda_runtime.h>
#include <cuda_bf16.h>

// Cumulative mean over axis 0 of x[8192, 4096] fp32:
//   out[r, c] = (sum_{i<=r} x[i, c]) / (r + 1)
//
// 3-pass reduce / segmented-scan:
//   pass1_sums : 16-row tile column sums -> g_part          (reads x, 5.9 TB/s)
//   pass2_seg  : fold 4 partials -> 64-row sums; segmented inclusive scan
//                (8 segments x 16 entries per column) -> g_s64 + g_segtot
//   pass3_out  : 64-row tiles; exclusive prefix = g_s64[rt-1] + earlier
//                segment totals; streaming scan + scale + __stcs store

#define ROWS   8192
#define COLS   4096
#define C4     (COLS / 4)             // 1024 float4 per row

#define TPB1   256
#define T1     16
#define NT1    (ROWS / T1)            // 512
#define NCB1   (COLS / (TPB1 * 4))    // 4

#define T3     64
#define NT3    (ROWS / T3)            // 128
#define SEGS   8
#define SEGLEN (NT3 / SEGS)           // 16

#define TPB3   128
#define NCB3   (COLS / (TPB3 * 4))    // 8

// Static device scratch (no allocation allowed anywhere).
__device__ float4 g_part[NT1 * C4];     // raw 16-row sums, 8 MB
__device__ float4 g_s64[NT3 * C4];      // segment-local inclusive prefixes, 2 MB
__device__ float4 g_segtot[SEGS * C4];  // per-segment totals, 128 KB
__device__ float  g_inv[ROWS];          // 1/(r+1)

__device__ __forceinline__ float4 f4_add(float4 a, float4 b) {
    a.x += b.x; a.y += b.y; a.z += b.z; a.w += b.w;
    return a;
}

// ---------------- Pass 1: 16-row tile partial sums (+ inv table) -------------
__global__ void __launch_bounds__(TPB1)
pass1_sums(const float* __restrict__ x) {
    const int bx  = blockIdx.x;
    const int rt  = bx / NCB1;
    const int cb  = bx % NCB1;
    const int tid = threadIdx.x;

    const int gt = bx * TPB1 + tid;
    if (gt < ROWS) g_inv[gt] = 1.0f / (float)(gt + 1);

    const float4* __restrict__ x4 = reinterpret_cast<const float4*>(x);
    const int col4 = cb * TPB1 + tid;
    const int base = rt * T1 * C4 + col4;

    float4 a0 = make_float4(0.f, 0.f, 0.f, 0.f);
    float4 a1 = a0, a2 = a0, a3 = a0;
#pragma unroll
    for (int r = 0; r < T1; r += 4) {
        float4 v0 = __ldg(&x4[base + (r + 0) * C4]);
        float4 v1 = __ldg(&x4[base + (r + 1) * C4]);
        float4 v2 = __ldg(&x4[base + (r + 2) * C4]);
        float4 v3 = __ldg(&x4[base + (r + 3) * C4]);
        a0 = f4_add(a0, v0);
        a1 = f4_add(a1, v1);
        a2 = f4_add(a2, v2);
        a3 = f4_add(a3, v3);
    }
    g_part[rt * C4 + col4] = f4_add(f4_add(a0, a1), f4_add(a2, a3));
}

// ------ Pass 2: segmented scan. 8192 threads: (segment, float4-column). ------
__global__ void __launch_bounds__(256)
pass2_seg() {
    const int gt   = blockIdx.x * 256 + threadIdx.x;  // 0..8191
    const int col4 = gt % C4;
    const int seg  = gt / C4;                         // 0..7
    const int e0   = seg * SEGLEN;                    // first 64-row entry

    float4 run = make_float4(0.f, 0.f, 0.f, 0.f);
#pragma unroll
    for (int g = 0; g < SEGLEN; g++) {
        const int p = (e0 + g) * 4;                   // first 16-row partial
        float4 s0 = __ldg(&g_part[(p + 0) * C4 + col4]);
        float4 s1 = __ldg(&g_part[(p + 1) * C4 + col4]);
        float4 s2 = __ldg(&g_part[(p + 2) * C4 + col4]);
        float4 s3 = __ldg(&g_part[(p + 3) * C4 + col4]);
        run = f4_add(run, f4_add(f4_add(s0, s1), f4_add(s2, s3)));
        g_s64[(e0 + g) * C4 + col4] = run;            // segment-local inclusive
    }
    g_segtot[seg * C4 + col4] = run;
}

// ---------------- Pass 3: streaming final scan + scale + store ---------------
__global__ void __launch_bounds__(TPB3)
pass3_out(const float* __restrict__ x, float* __restrict__ out) {
    const int bx  = blockIdx.x;
    const int rt  = bx / NCB3;            // 64-row tile (0..127)
    const int cb  = bx % NCB3;
    const int tid = threadIdx.x;

    const float4* __restrict__ x4 = reinterpret_cast<const float4*>(x);
    float4*       __restrict__ o4 = reinterpret_cast<float4*>(out);
    const int col4 = cb * TPB3 + tid;
    const int base = rt * T3 * C4 + col4;
    const int row0 = rt * T3;

    // Exclusive prefix = seg-local inclusive of entry rt-1 + earlier seg totals.
    float4 run = make_float4(0.f, 0.f, 0.f, 0.f);
    if (rt > 0) {
        const int e   = rt - 1;
        const int seg = e / SEGLEN;
        run = __ldg(&g_s64[e * C4 + col4]);
#pragma unroll
        for (int s = 0; s < SEGS - 1; s++) {
            if (s < seg) run = f4_add(run, __ldg(&g_segtot[s * C4 + col4]));
        }
    }

#pragma unroll 4
    for (int r = 0; r < T3; r += 4) {
        float4 v0 = __ldg(&x4[base + (r + 0) * C4]);
        float4 v1 = __ldg(&x4[base + (r + 1) * C4]);
        float4 v2 = __ldg(&x4[base + (r + 2) * C4]);
        float4 v3 = __ldg(&x4[base + (r + 3) * C4]);

        const float i0 = g_inv[row0 + r + 0];
        const float i1 = g_inv[row0 + r + 1];
        const float i2 = g_inv[row0 + r + 2];
        const float i3 = g_inv[row0 + r + 3];

        float4 o;
        run = f4_add(run, v0);
        o.x = run.x * i0; o.y = run.y * i0; o.z = run.z * i0; o.w = run.w * i0;
        __stcs(&o4[base + (r + 0) * C4], o);

        run = f4_add(run, v1);
        o.x = run.x * i1; o.y = run.y * i1; o.z = run.z * i1; o.w = run.w * i1;
        __stcs(&o4[base + (r + 1) * C4], o);

        run = f4_add(run, v2);
        o.x = run.x * i2; o.y = run.y * i2; o.z = run.z * i2; o.w = run.w * i2;
        __stcs(&o4[base + (r + 2) * C4], o);

        run = f4_add(run, v3);
        o.x = run.x * i3; o.y = run.y * i3; o.z = run.z * i3; o.w = run.w * i3;
        __stcs(&o4[base + (r + 3) * C4], o);
    }
}

extern "C" void kernel_launch(void* const* d_in, const int* in_sizes, int n_in,
                              void* d_out, int out_size) {
    const float* x   = (const float*)d_in[0];
    float*       out = (float*)d_out;

    pass1_sums<<<NT1 * NCB1, TPB1>>>(x);
    pass2_seg<<<(SEGS * C4) / 256, 256>>>();
    pass3_out<<<NT3 * NCB3, TPB3>>>(x, out);
}

// round 14
// speedup vs baseline: 1.6742x; 1.0172x over previous
#include <cuda_runtime.h>
#include <cuda_bf16.h>

// Cumulative mean over axis 0 of x[8192, 4096] fp32:
//   out[r, c] = (sum_{i<=r} x[i, c]) / (r + 1)
//
// 3-pass reduce / segmented-scan:
//   pass1_sums : 16-row tile column sums -> g_part          (reads x, 5.9 TB/s)
//   pass2_seg  : fold 4 partials -> 64-row sums; segmented inclusive scan
//                (8 segments x 16 entries per column) -> g_s64 + g_segtot
//   pass3_out  : 64-row tiles; exclusive prefix = g_s64[rt-1] + earlier
//                segment totals; streaming scan + scale + __stcs store

#define ROWS   8192
#define COLS   4096
#define C4     (COLS / 4)             // 1024 float4 per row

#define TPB1   256
#define T1     16
#define NT1    (ROWS / T1)            // 512
#define NCB1   (COLS / (TPB1 * 4))    // 4

#define T3     64
#define NT3    (ROWS / T3)            // 128
#define SEGS   8
#define SEGLEN (NT3 / SEGS)           // 16

#define TPB3   128
#define NCB3   (COLS / (TPB3 * 4))    // 8

// Static device scratch (no allocation allowed anywhere).
__device__ float4 g_part[NT1 * C4];     // raw 16-row sums, 8 MB
__device__ float4 g_s64[NT3 * C4];      // segment-local inclusive prefixes, 2 MB
__device__ float4 g_segtot[SEGS * C4];  // per-segment totals, 128 KB
__device__ float  g_inv[ROWS];          // 1/(r+1)

__device__ __forceinline__ float4 f4_add(float4 a, float4 b) {
    a.x += b.x; a.y += b.y; a.z += b.z; a.w += b.w;
    return a;
}

// ---------------- Pass 1: 16-row tile partial sums (+ inv table) -------------
__global__ void __launch_bounds__(TPB1)
pass1_sums(const float* __restrict__ x) {
    const int bx  = blockIdx.x;
    const int rt  = bx / NCB1;
    const int cb  = bx % NCB1;
    const int tid = threadIdx.x;

    const int gt = bx * TPB1 + tid;
    if (gt < ROWS) g_inv[gt] = 1.0f / (float)(gt + 1);

    const float4* __restrict__ x4 = reinterpret_cast<const float4*>(x);
    const int col4 = cb * TPB1 + tid;
    const int base = rt * T1 * C4 + col4;

    float4 a0 = make_float4(0.f, 0.f, 0.f, 0.f);
    float4 a1 = a0, a2 = a0, a3 = a0;
#pragma unroll
    for (int r = 0; r < T1; r += 4) {
        float4 v0 = __ldg(&x4[base + (r + 0) * C4]);
        float4 v1 = __ldg(&x4[base + (r + 1) * C4]);
        float4 v2 = __ldg(&x4[base + (r + 2) * C4]);
        float4 v3 = __ldg(&x4[base + (r + 3) * C4]);
        a0 = f4_add(a0, v0);
        a1 = f4_add(a1, v1);
        a2 = f4_add(a2, v2);
        a3 = f4_add(a3, v3);
    }
    g_part[rt * C4 + col4] = f4_add(f4_add(a0, a1), f4_add(a2, a3));
}

// ------ Pass 2: segmented scan. 8192 threads: (segment, float4-column). ------
__global__ void __launch_bounds__(256)
pass2_seg() {
    const int gt   = blockIdx.x * 256 + threadIdx.x;  // 0..8191
    const int col4 = gt % C4;
    const int seg  = gt / C4;                         // 0..7
    const int e0   = seg * SEGLEN;                    // first 64-row entry

    float4 run = make_float4(0.f, 0.f, 0.f, 0.f);
#pragma unroll
    for (int g = 0; g < SEGLEN; g++) {
        const int p = (e0 + g) * 4;                   // first 16-row partial
        float4 s0 = __ldg(&g_part[(p + 0) * C4 + col4]);
        float4 s1 = __ldg(&g_part[(p + 1) * C4 + col4]);
        float4 s2 = __ldg(&g_part[(p + 2) * C4 + col4]);
        float4 s3 = __ldg(&g_part[(p + 3) * C4 + col4]);
        run = f4_add(run, f4_add(f4_add(s0, s1), f4_add(s2, s3)));
        g_s64[(e0 + g) * C4 + col4] = run;            // segment-local inclusive
    }
    g_segtot[seg * C4 + col4] = run;
}

// ---------------- Pass 3: streaming final scan + scale + store ---------------
__global__ void __launch_bounds__(TPB3)
pass3_out(const float* __restrict__ x, float* __restrict__ out) {
    const int bx  = blockIdx.x;
    const int rt  = bx / NCB3;            // 64-row tile (0..127)
    const int cb  = bx % NCB3;
    const int tid = threadIdx.x;

    const float4* __restrict__ x4 = reinterpret_cast<const float4*>(x);
    float4*       __restrict__ o4 = reinterpret_cast<float4*>(out);
    const int col4 = cb * TPB3 + tid;
    const int base = rt * T3 * C4 + col4;
    const int row0 = rt * T3;

    // Exclusive prefix = seg-local inclusive of entry rt-1 + earlier seg totals.
    float4 run = make_float4(0.f, 0.f, 0.f, 0.f);
    if (rt > 0) {
        const int e   = rt - 1;
        const int seg = e / SEGLEN;
        run = __ldg(&g_s64[e * C4 + col4]);
#pragma unroll
        for (int s = 0; s < SEGS - 1; s++) {
            if (s < seg) run = f4_add(run, __ldg(&g_segtot[s * C4 + col4]));
        }
    }

#pragma unroll 4
    for (int r = 0; r < T3; r += 4) {
        float4 v0 = __ldg(&x4[base + (r + 0) * C4]);
        float4 v1 = __ldg(&x4[base + (r + 1) * C4]);
        float4 v2 = __ldg(&x4[base + (r + 2) * C4]);
        float4 v3 = __ldg(&x4[base + (r + 3) * C4]);

        const float i0 = g_inv[row0 + r + 0];
        const float i1 = g_inv[row0 + r + 1];
        const float i2 = g_inv[row0 + r + 2];
        const float i3 = g_inv[row0 + r + 3];

        float4 o;
        run = f4_add(run, v0);
        o.x = run.x * i0; o.y = run.y * i0; o.z = run.z * i0; o.w = run.w * i0;
        __stcs(&o4[base + (r + 0) * C4], o);

        run = f4_add(run, v1);
        o.x = run.x * i1; o.y = run.y * i1; o.z = run.z * i1; o.w = run.w * i1;
        __stcs(&o4[base + (r + 1) * C4], o);

        run = f4_add(run, v2);
        o.x = run.x * i2; o.y = run.y * i2; o.z = run.z * i2; o.w = run.w * i2;
        __stcs(&o4[base + (r + 2) * C4], o);

        run = f4_add(run, v3);
        o.x = run.x * i3; o.y = run.y * i3; o.z = run.z * i3; o.w = run.w * i3;
        __stcs(&o4[base + (r + 3) * C4], o);
    }
}

extern "C" void kernel_launch(void* const* d_in, const int* in_sizes, int n_in,
                              void* d_out, int out_size) {
    const float* x   = (const float*)d_in[0];
    float*       out = (float*)d_out;

    pass1_sums<<<NT1 * NCB1, TPB1>>>(x);
    pass2_seg<<<(SEGS * C4) / 256, 256>>>();
    pass3_out<<<NT3 * NCB3, TPB3>>>(x, out);
}

// round 15
// speedup vs baseline: 1.7396x; 1.0391x over previous
#include <cuda_runtime.h>
#include <cuda_bf16.h>

// Cumulative mean over axis 0 of x[8192, 4096] fp32:
//   out[r, c] = (sum_{i<=r} x[i, c]) / (r + 1)
//
// 3-pass reduce / segmented-scan:
//   pass1_sums : 32-row tile column sums -> g_p32 (4 MB)    [one wave, 5.8 TB/s]
//   pass2_seg  : scalar columns; fold 2 partials -> 64-row sums; segmented
//                inclusive scan (8 segs x 16 entries) -> g_s64 + g_segtot
//   pass3_out  : 64-row tiles; excl prefix = g_s64[rt-1] + earlier segment
//                totals; streaming scan + scale + __stcs store

#define ROWS   8192
#define COLS   4096
#define C4     (COLS / 4)             // 1024 float4 per row

// ---- pass 1 geometry: ONE wave (1024 blocks x 256 thr = 262144 threads) ----
#define TPB1   256
#define T1     32
#define NT1    (ROWS / T1)            // 256 thirty-two-row tiles
#define NCB1   (COLS / (TPB1 * 4))    // 4

// ---- 64-row scan geometry ----
#define T3     64
#define NT3    (ROWS / T3)            // 128
#define SEGS   8
#define SEGLEN (NT3 / SEGS)           // 16 entries per segment

// ---- pass 3 geometry (proven at mixed-stream floor) ----
#define TPB3   128
#define NCB3   (COLS / (TPB3 * 4))    // 8

// Static device scratch (no allocation allowed anywhere).
__device__ float4 g_p32[NT1 * C4];      // 32-row sums, 4 MB
__device__ float  g_s64[NT3 * COLS];    // segment-local inclusive prefixes, 2 MB
__device__ float  g_segtot[SEGS * COLS];// per-segment totals, 128 KB
__device__ float  g_inv[ROWS];          // 1/(r+1)

__device__ __forceinline__ float4 f4_add(float4 a, float4 b) {
    a.x += b.x; a.y += b.y; a.z += b.z; a.w += b.w;
    return a;
}

// ---------------- Pass 1: 32-row tile partial sums (+ inv table) -------------
__global__ void __launch_bounds__(TPB1)
pass1_sums(const float* __restrict__ x) {
    const int bx  = blockIdx.x;
    const int rt  = bx / NCB1;
    const int cb  = bx % NCB1;
    const int tid = threadIdx.x;

    const int gt = bx * TPB1 + tid;
    if (gt < ROWS) g_inv[gt] = 1.0f / (float)(gt + 1);

    const float4* __restrict__ x4 = reinterpret_cast<const float4*>(x);
    const int col4 = cb * TPB1 + tid;
    const int base = rt * T1 * C4 + col4;

    float4 a0 = make_float4(0.f, 0.f, 0.f, 0.f);
    float4 a1 = a0, a2 = a0, a3 = a0;
#pragma unroll
    for (int r = 0; r < T1; r += 4) {
        float4 v0 = __ldg(&x4[base + (r + 0) * C4]);
        float4 v1 = __ldg(&x4[base + (r + 1) * C4]);
        float4 v2 = __ldg(&x4[base + (r + 2) * C4]);
        float4 v3 = __ldg(&x4[base + (r + 3) * C4]);
        a0 = f4_add(a0, v0);
        a1 = f4_add(a1, v1);
        a2 = f4_add(a2, v2);
        a3 = f4_add(a3, v3);
    }
    g_p32[rt * C4 + col4] = f4_add(f4_add(a0, a1), f4_add(a2, a3));
}

// ---- Pass 2: segmented scan. 32768 threads (128 blocks): (seg, scalar col). -
__global__ void __launch_bounds__(256)
pass2_seg() {
    const float* gp = reinterpret_cast<const float*>(g_p32); // [NT1][COLS]
    const int gt  = blockIdx.x * 256 + threadIdx.x;          // 0..32767
    const int col = gt % COLS;
    const int seg = gt / COLS;                               // 0..7
    const int e0  = seg * SEGLEN;                            // first 64-row entry

    float run = 0.f;
    // 4 batches of 4 entries; each entry = 2 thirty-two-row partials.
#pragma unroll
    for (int b = 0; b < SEGLEN; b += 4) {
        float v[8];
#pragma unroll
        for (int j = 0; j < 8; j++)
            v[j] = __ldg(&gp[((e0 + b) * 2 + j) * COLS + col]);  // 8 indep loads
#pragma unroll
        for (int g = 0; g < 4; g++) {
            run += v[g * 2 + 0] + v[g * 2 + 1];
            g_s64[(e0 + b + g) * COLS + col] = run;          // seg-local inclusive
        }
    }
    g_segtot[seg * COLS + col] = run;
}

// ---------------- Pass 3: streaming final scan + scale + store ---------------
__global__ void __launch_bounds__(TPB3)
pass3_out(const float* __restrict__ x, float* __restrict__ out) {
    const int bx  = blockIdx.x;
    const int rt  = bx / NCB3;            // 64-row tile (0..127)
    const int cb  = bx % NCB3;
    const int tid = threadIdx.x;

    const float4* __restrict__ x4 = reinterpret_cast<const float4*>(x);
    float4*       __restrict__ o4 = reinterpret_cast<float4*>(out);
    const int col4 = cb * TPB3 + tid;
    const int base = rt * T3 * C4 + col4;
    const int row0 = rt * T3;

    // Exclusive prefix = seg-local inclusive of entry rt-1 + earlier seg totals.
    float4 run = make_float4(0.f, 0.f, 0.f, 0.f);
    if (rt > 0) {
        const int e   = rt - 1;
        const int seg = e / SEGLEN;
        run = __ldg(&reinterpret_cast<const float4*>(g_s64)[e * C4 + col4]);
        const float4* st4 = reinterpret_cast<const float4*>(g_segtot);
#pragma unroll
        for (int s = 0; s < SEGS - 1; s++) {
            if (s < seg) run = f4_add(run, __ldg(&st4[s * C4 + col4]));
        }
    }

#pragma unroll 4
    for (int r = 0; r < T3; r += 4) {
        float4 v0 = __ldg(&x4[base + (r + 0) * C4]);
        float4 v1 = __ldg(&x4[base + (r + 1) * C4]);
        float4 v2 = __ldg(&x4[base + (r + 2) * C4]);
        float4 v3 = __ldg(&x4[base + (r + 3) * C4]);

        const float i0 = g_inv[row0 + r + 0];
        const float i1 = g_inv[row0 + r + 1];
        const float i2 = g_inv[row0 + r + 2];
        const float i3 = g_inv[row0 + r + 3];

        float4 o;
        run = f4_add(run, v0);
        o.x = run.x * i0; o.y = run.y * i0; o.z = run.z * i0; o.w = run.w * i0;
        __stcs(&o4[base + (r + 0) * C4], o);

        run = f4_add(run, v1);
        o.x = run.x * i1; o.y = run.y * i1; o.z = run.z * i1; o.w = run.w * i1;
        __stcs(&o4[base + (r + 1) * C4], o);

        run = f4_add(run, v2);
        o.x = run.x * i2; o.y = run.y * i2; o.z = run.z * i2; o.w = run.w * i2;
        __stcs(&o4[base + (r + 2) * C4], o);

        run = f4_add(run, v3);
        o.x = run.x * i3; o.y = run.y * i3; o.z = run.z * i3; o.w = run.w * i3;
        __stcs(&o4[base + (r + 3) * C4], o);
    }
}

extern "C" void kernel_launch(void* const* d_in, const int* in_sizes, int n_in,
                              void* d_out, int out_size) {
    const float* x   = (const float*)d_in[0];
    float*       out = (float*)d_out;

    pass1_sums<<<NT1 * NCB1, TPB1>>>(x);
    pass2_seg<<<(SEGS * COLS) / 256, 256>>>();
    pass3_out<<<NT3 * NCB3, TPB3>>>(x, out);
}